// round 9
// baseline (speedup 1.0000x reference)
#include <cuda_runtime.h>
#include <cstdint>

// ---------------- problem constants ----------------
#define B_DIM 4096
#define H_DIM 2048
#define C_DIM 4096              // K dimension (H + I)
#define TM 128                  // CTA M tile
#define TN 64                   // CTA N tile (per gate; x4 gates computed together)
#define TK 32                   // K per stage
#define KSTAGES (C_DIM / TK)    // 128
#define NS 4                    // pipeline stages
#define NTHREADS 512            // 16 warps: 4 over M x 4 over N

// padded smem layout: rows of 36 floats (144B) -> conflict-free frag loads
#define ROWF 36
#define A_FLOATS (TM * ROWF)            // 4608 floats = 18432 B
#define BG_FLOATS (TN * ROWF)           // 2304 floats = 9216 B
#define STAGE_FLOATS (A_FLOATS + 4 * BG_FLOATS)   // 13824 floats = 55296 B
#define SMEM_TOTAL (NS * STAGE_FLOATS * 4)        // 221184 B

#define HOUT_OFF 8388608        // 4096*2048 ; c_t follows h_t in d_out

// ---------- pre-rounded (tf32-rna) operand scratch: static device globals ----------
__device__ float g_W[4ll * 2048 * 4096];   // 4 gates x [2048][4096]
__device__ float g_A[4096ll * 4096];       // [B][h_prev | x_t]

__device__ __forceinline__ uint32_t smem_u32(const void* p) {
    uint32_t a;
    asm("{ .reg .u64 t; cvta.to.shared.u64 t, %1; cvt.u32.u64 %0, t; }" : "=r"(a) : "l"(p));
    return a;
}

#define CP_ASYNC16(dst, src) \
    asm volatile("cp.async.cg.shared.global [%0], [%1], 16;" :: "r"(dst), "l"(src) : "memory")
#define CP_COMMIT() asm volatile("cp.async.commit_group;" ::: "memory")
#define CP_WAIT2()  asm volatile("cp.async.wait_group 2;" ::: "memory")

__device__ __forceinline__ float f2tf32f(float x) {
    uint32_t r;
    asm("cvt.rna.tf32.f32 %0, %1;" : "=r"(r) : "f"(x));
    return __uint_as_float(r);
}

__device__ __forceinline__ void mma_tf32(float* c, const uint32_t* a, const uint32_t* b) {
    asm volatile(
        "mma.sync.aligned.m16n8k8.row.col.f32.tf32.tf32.f32 "
        "{%0,%1,%2,%3}, {%4,%5,%6,%7}, {%8,%9}, {%0,%1,%2,%3};"
        : "+f"(c[0]), "+f"(c[1]), "+f"(c[2]), "+f"(c[3])
        : "r"(a[0]), "r"(a[1]), "r"(a[2]), "r"(a[3]), "r"(b[0]), "r"(b[1]));
}

__device__ __forceinline__ float sigmoidf_(float x) {
    return 1.0f / (1.0f + __expf(-x));
}
__device__ __forceinline__ float tanhf_(float x) {
    float a = fabsf(x);
    float e = __expf(-2.0f * a);
    float t = (1.0f - e) / (1.0f + e);
    return x < 0.0f ? -t : t;
}

// ---------------- prepass: round everything to tf32 (rna) once ----------------
#define W_F4 8388608
#define A_F4 4194304
#define TOT_F4 (W_F4 + A_F4)

__global__ void __launch_bounds__(256) prepass_kernel(
    const float4* __restrict__ x_t, const float4* __restrict__ h_prev,
    const float4* __restrict__ Wf, const float4* __restrict__ Wi,
    const float4* __restrict__ Wc, const float4* __restrict__ Wo)
{
    float4* __restrict__ gw = (float4*)g_W;
    float4* __restrict__ ga = (float4*)g_A;
    const int stride = gridDim.x * blockDim.x;
    for (long long i = blockIdx.x * blockDim.x + threadIdx.x; i < TOT_F4; i += stride) {
        float4 v;
        float4* dst;
        if (i < W_F4) {
            const long long g = i >> 21;
            const long long r = i & 2097151;
            const float4* wp = (g == 0) ? Wf : (g == 1) ? Wi : (g == 2) ? Wc : Wo;
            v = wp[r];
            dst = gw + i;
        } else {
            const long long j = i - W_F4;
            const long long row = j >> 10;
            const long long c4 = j & 1023;
            v = (c4 < 512) ? h_prev[row * 512 + c4] : x_t[row * 512 + (c4 - 512)];
            dst = ga + j;
        }
        v.x = f2tf32f(v.x); v.y = f2tf32f(v.y);
        v.z = f2tf32f(v.z); v.w = f2tf32f(v.w);
        *dst = v;
    }
}

// issue cp.async for one K-stage (all 512 threads participate)
__device__ __forceinline__ void load_stage(int ks, int stage, int tid, uint32_t sbase,
                                           int m0, int n0)
{
    const int k0 = ks * TK;
    const uint32_t stg = sbase + (uint32_t)stage * (STAGE_FLOATS * 4);
    const float* asrc = g_A + (size_t)m0 * C_DIM + k0;
    // A tile: 128 rows x 8 x 16B chunks = 1024; 2 per thread
    #pragma unroll
    for (int i = 0; i < 2; i++) {
        const int c = tid + i * NTHREADS;
        const int row = c >> 3;
        const int c16 = c & 7;
        const uint32_t dst = stg + (uint32_t)(row * (ROWF * 4) + c16 * 16);
        CP_ASYNC16(dst, asrc + (size_t)row * C_DIM + c16 * 4);
    }
    // W tiles: 4 gates x 64 rows x 8 chunks = 2048; 4 per thread
    #pragma unroll
    for (int i = 0; i < 4; i++) {
        const int idx = tid + i * NTHREADS;      // 0..2047
        const int g = idx >> 9;
        const int rem = idx & 511;
        const int row = rem >> 3;
        const int c16 = rem & 7;
        const float* wp = g_W + (size_t)g * (2048ll * 4096);
        const uint32_t dst = stg + (uint32_t)(A_FLOATS * 4 + g * (BG_FLOATS * 4)
                                              + row * (ROWF * 4) + c16 * 16);
        CP_ASYNC16(dst, wp + (size_t)(n0 + row) * C_DIM + k0 + c16 * 4);
    }
}

__global__ void __launch_bounds__(NTHREADS, 1) lstm_mma_kernel(
    const float* __restrict__ c_prev,
    const float* __restrict__ bf, const float* __restrict__ bi,
    const float* __restrict__ bc, const float* __restrict__ bo,
    float* __restrict__ out)
{
    extern __shared__ float smemf[];
    const uint32_t sbase = smem_u32(smemf);
    const int tid = threadIdx.x;
    const int wid = tid >> 5;
    const int lane = tid & 31;
    const int wm = wid & 3;      // 4 warps over M (32 rows each)
    const int wn = wid >> 2;     // 4 warps over N (16 cols each)
    const int gid = lane >> 2;   // mma groupID
    const int tig = lane & 3;    // mma threadID_in_group
    const int m0 = blockIdx.x * TM;
    const int n0 = blockIdx.y * TN;

    // accumulators: [gate][mt][nt][4]  (mt: 2x16 rows, nt: 2x8 cols)
    float acc[4][2][2][4];
    #pragma unroll
    for (int g = 0; g < 4; g++)
        #pragma unroll
        for (int mt = 0; mt < 2; mt++)
            #pragma unroll
            for (int nt = 0; nt < 2; nt++)
                #pragma unroll
                for (int r = 0; r < 4; r++) acc[g][mt][nt][r] = 0.0f;

    #pragma unroll
    for (int s = 0; s < NS - 1; s++) {
        load_stage(s, s, tid, sbase, m0, n0);
        CP_COMMIT();
    }

    #pragma unroll 1
    for (int ks = 0; ks < KSTAGES; ks++) {
        CP_WAIT2();
        __syncthreads();
        const int stage = ks & (NS - 1);
        const uint32_t* As = (const uint32_t*)(smemf + stage * STAGE_FLOATS);
        const uint32_t* Bs = As + A_FLOATS;

        #pragma unroll
        for (int kk = 0; kk < 4; kk++) {
            const int kc = kk * 8;
            uint32_t afr[2][4];
            #pragma unroll
            for (int mt = 0; mt < 2; mt++) {
                const int r0 = wm * 32 + mt * 16 + gid;
                afr[mt][0] = As[r0 * ROWF + kc + tig];
                afr[mt][1] = As[(r0 + 8) * ROWF + kc + tig];
                afr[mt][2] = As[r0 * ROWF + kc + tig + 4];
                afr[mt][3] = As[(r0 + 8) * ROWF + kc + tig + 4];
            }
            #pragma unroll
            for (int g = 0; g < 4; g++) {
                const uint32_t* Bg = Bs + g * BG_FLOATS;
                uint32_t bfr[2][2];
                #pragma unroll
                for (int nt = 0; nt < 2; nt++) {
                    const int nb = wn * 16 + nt * 8 + gid;
                    bfr[nt][0] = Bg[nb * ROWF + kc + tig];
                    bfr[nt][1] = Bg[nb * ROWF + kc + tig + 4];
                }
                #pragma unroll
                for (int mt = 0; mt < 2; mt++)
                    #pragma unroll
                    for (int nt = 0; nt < 2; nt++)
                        mma_tf32(acc[g][mt][nt], afr[mt], bfr[nt]);
            }
        }
        __syncthreads();
        if (ks + NS - 1 < KSTAGES) {
            load_stage(ks + NS - 1, (ks + NS - 1) & (NS - 1), tid, sbase, m0, n0);
            CP_COMMIT();
        }
    }

    // ---------------- fused LSTM epilogue (registers only) ----------------
    #pragma unroll
    for (int nt = 0; nt < 2; nt++) {
        const int col = n0 + wn * 16 + nt * 8 + tig * 2;
        const float2 bf2 = *(const float2*)(bf + col);
        const float2 bi2 = *(const float2*)(bi + col);
        const float2 bc2 = *(const float2*)(bc + col);
        const float2 bo2 = *(const float2*)(bo + col);
        #pragma unroll
        for (int mt = 0; mt < 2; mt++) {
            const int row0 = m0 + wm * 32 + mt * 16 + gid;
            #pragma unroll
            for (int half = 0; half < 2; half++) {
                const int row = row0 + half * 8;
                const int ci = half * 2;
                const float2 cp = *(const float2*)(c_prev + (size_t)row * H_DIM + col);
                float hh[2], cc[2];
                #pragma unroll
                for (int j = 0; j < 2; j++) {
                    const float gf = acc[0][mt][nt][ci + j] + (j ? bf2.y : bf2.x);
                    const float gi = acc[1][mt][nt][ci + j] + (j ? bi2.y : bi2.x);
                    const float gc = acc[2][mt][nt][ci + j] + (j ? bc2.y : bc2.x);
                    const float go = acc[3][mt][nt][ci + j] + (j ? bo2.y : bo2.x);
                    const float f = sigmoidf_(gf);
                    const float i = sigmoidf_(gi);
                    const float ct = tanhf_(gc);
                    const float o = sigmoidf_(go);
                    const float c = f * (j ? cp.y : cp.x) + i * ct;
                    cc[j] = c;
                    hh[j] = o * tanhf_(c);
                }
                *(float2*)(out + (size_t)row * H_DIM + col) = make_float2(hh[0], hh[1]);
                *(float2*)(out + HOUT_OFF + (size_t)row * H_DIM + col) = make_float2(cc[0], cc[1]);
            }
        }
    }
}

extern "C" void kernel_launch(void* const* d_in, const int* in_sizes, int n_in,
                              void* d_out, int out_size) {
    const float* x_t    = (const float*)d_in[0];
    const float* h_prev = (const float*)d_in[1];
    const float* c_prev = (const float*)d_in[2];
    const float* W_f    = (const float*)d_in[3];
    const float* b_f    = (const float*)d_in[4];
    const float* W_i    = (const float*)d_in[5];
    const float* b_i    = (const float*)d_in[6];
    const float* W_c    = (const float*)d_in[7];
    const float* b_c    = (const float*)d_in[8];
    const float* W_o    = (const float*)d_in[9];
    const float* b_o    = (const float*)d_in[10];
    float* out = (float*)d_out;

    // 1) round all GEMM operands to tf32 once
    prepass_kernel<<<2048, 256>>>(
        (const float4*)x_t, (const float4*)h_prev,
        (const float4*)W_f, (const float4*)W_i,
        (const float4*)W_c, (const float4*)W_o);

    // 2) fused GEMM + LSTM epilogue
    cudaFuncSetAttribute(lstm_mma_kernel,
                         cudaFuncAttributeMaxDynamicSharedMemorySize, SMEM_TOTAL);
    dim3 grid(B_DIM / TM, H_DIM / TN);   // (32, 32)
    lstm_mma_kernel<<<grid, NTHREADS, SMEM_TOTAL>>>(
        c_prev, b_f, b_i, b_c, b_o, out);
}

// round 10
// speedup vs baseline: 1.0498x; 1.0498x over previous
#include <cuda_runtime.h>
#include <cstdint>

// ---------------- problem constants ----------------
#define B_DIM 4096
#define H_DIM 2048
#define C_DIM 4096              // K dimension (H + I)
#define TM 128                  // CTA M tile
#define TN 64                   // CTA N tile (per gate; x4 gates)
#define TK 32                   // K per stage
#define KSTAGES (C_DIM / TK)    // 128
#define NS 4                    // pipeline stages
#define NTHREADS 256            // 8 warps: 2 over M x 4 over N

// padded smem layout: rows of 36 floats (144B) -> conflict-free frag loads
#define ROWF 36
#define A_FLOATS (TM * ROWF)            // 4608 floats
#define BG_FLOATS (TN * ROWF)           // 2304 floats
#define STAGE_FLOATS (A_FLOATS + 4 * BG_FLOATS)   // 13824 floats = 55296 B
#define SMEM_TOTAL (NS * STAGE_FLOATS * 4)        // 221184 B

#define HOUT_OFF 8388608        // 4096*2048 ; c_t follows h_t in d_out

// ---------- pre-rounded (tf32-rna) operand scratch ----------
__device__ float g_W[4ll * 2048 * 4096];   // 4 gates x [2048][4096]
__device__ float g_A[4096ll * 4096];       // [B][h_prev | x_t]

__device__ __forceinline__ uint32_t smem_u32(const void* p) {
    uint32_t a;
    asm("{ .reg .u64 t; cvta.to.shared.u64 t, %1; cvt.u32.u64 %0, t; }" : "=r"(a) : "l"(p));
    return a;
}

#define CP_ASYNC16(dst, src) \
    asm volatile("cp.async.cg.shared.global [%0], [%1], 16;" :: "r"(dst), "l"(src) : "memory")
#define CP_COMMIT() asm volatile("cp.async.commit_group;" ::: "memory")
#define CP_WAIT2()  asm volatile("cp.async.wait_group 2;" ::: "memory")
#define CP_WAIT0()  asm volatile("cp.async.wait_group 0;" ::: "memory")

__device__ __forceinline__ float f2tf32f(float x) {
    uint32_t r;
    asm("cvt.rna.tf32.f32 %0, %1;" : "=r"(r) : "f"(x));
    return __uint_as_float(r);
}

__device__ __forceinline__ void mma_tf32(float* c, const uint32_t* a, const uint32_t* b) {
    asm volatile(
        "mma.sync.aligned.m16n8k8.row.col.f32.tf32.tf32.f32 "
        "{%0,%1,%2,%3}, {%4,%5,%6,%7}, {%8,%9}, {%0,%1,%2,%3};"
        : "+f"(c[0]), "+f"(c[1]), "+f"(c[2]), "+f"(c[3])
        : "r"(a[0]), "r"(a[1]), "r"(a[2]), "r"(a[3]), "r"(b[0]), "r"(b[1]));
}

__device__ __forceinline__ float sigmoidf_(float x) {
    return 1.0f / (1.0f + __expf(-x));
}
__device__ __forceinline__ float tanhf_(float x) {
    float a = fabsf(x);
    float e = __expf(-2.0f * a);
    float t = (1.0f - e) / (1.0f + e);
    return x < 0.0f ? -t : t;
}

// ---------------- prepass: round everything to tf32 (rna) once ----------------
#define W_F4 8388608
#define A_F4 4194304
#define TOT_F4 (W_F4 + A_F4)

__global__ void __launch_bounds__(256) prepass_kernel(
    const float4* __restrict__ x_t, const float4* __restrict__ h_prev,
    const float4* __restrict__ Wf, const float4* __restrict__ Wi,
    const float4* __restrict__ Wc, const float4* __restrict__ Wo)
{
    float4* __restrict__ gw = (float4*)g_W;
    float4* __restrict__ ga = (float4*)g_A;
    const int stride = gridDim.x * blockDim.x;
    for (long long i = blockIdx.x * blockDim.x + threadIdx.x; i < TOT_F4; i += stride) {
        float4 v;
        float4* dst;
        if (i < W_F4) {
            const long long g = i >> 21;
            const long long r = i & 2097151;
            const float4* wp = (g == 0) ? Wf : (g == 1) ? Wi : (g == 2) ? Wc : Wo;
            v = wp[r];
            dst = gw + i;
        } else {
            const long long j = i - W_F4;
            const long long row = j >> 10;
            const long long c4 = j & 1023;
            v = (c4 < 512) ? h_prev[row * 512 + c4] : x_t[row * 512 + (c4 - 512)];
            dst = ga + j;
        }
        v.x = f2tf32f(v.x); v.y = f2tf32f(v.y);
        v.z = f2tf32f(v.z); v.w = f2tf32f(v.w);
        *dst = v;
    }
}

// issue cp.async for one K-stage (all 256 threads participate)
__device__ __forceinline__ void load_stage(int ks, int stage, int tid, uint32_t sbase,
                                           int m0, int n0)
{
    const int k0 = ks * TK;
    const uint32_t stg = sbase + (uint32_t)stage * (STAGE_FLOATS * 4);
    const float* asrc = g_A + (size_t)m0 * C_DIM + k0;
    // A tile: 128 rows x 8 x 16B chunks = 1024; 4 per thread
    #pragma unroll
    for (int i = 0; i < 4; i++) {
        const int c = tid + i * NTHREADS;
        const int row = c >> 3;
        const int c16 = c & 7;
        const uint32_t dst = stg + (uint32_t)(row * (ROWF * 4) + c16 * 16);
        CP_ASYNC16(dst, asrc + (size_t)row * C_DIM + c16 * 4);
    }
    // W tiles: 4 gates x 64 rows x 8 chunks = 2048; 8 per thread
    #pragma unroll
    for (int i = 0; i < 8; i++) {
        const int idx = tid + i * NTHREADS;      // 0..2047
        const int g = idx >> 9;
        const int rem = idx & 511;
        const int row = rem >> 3;
        const int c16 = rem & 7;
        const float* wp = g_W + (size_t)g * (2048ll * 4096);
        const uint32_t dst = stg + (uint32_t)(A_FLOATS * 4 + g * (BG_FLOATS * 4)
                                              + row * (ROWF * 4) + c16 * 16);
        CP_ASYNC16(dst, wp + (size_t)(n0 + row) * C_DIM + k0 + c16 * 4);
    }
}

__global__ void __launch_bounds__(NTHREADS, 1) lstm_mma_kernel(
    const float* __restrict__ c_prev,
    const float* __restrict__ bf, const float* __restrict__ bi,
    const float* __restrict__ bc, const float* __restrict__ bo,
    float* __restrict__ out)
{
    extern __shared__ float smemf[];
    const uint32_t sbase = smem_u32(smemf);
    const int tid = threadIdx.x;
    const int wid = tid >> 5;
    const int lane = tid & 31;
    const int wm = wid & 1;      // 2 warps over M (64 rows each, mt=4)
    const int wn = wid >> 1;     // 4 warps over N (16 cols each, nt=2)
    const int gid = lane >> 2;   // mma groupID
    const int tig = lane & 3;    // mma threadID_in_group
    const int m0 = blockIdx.x * TM;
    const int n0 = blockIdx.y * TN;

    // accumulators: [gate][mt=4][nt=2][4] = 128 floats
    float acc[4][4][2][4];
    #pragma unroll
    for (int g = 0; g < 4; g++)
        #pragma unroll
        for (int mt = 0; mt < 4; mt++)
            #pragma unroll
            for (int nt = 0; nt < 2; nt++)
                #pragma unroll
                for (int r = 0; r < 4; r++) acc[g][mt][nt][r] = 0.0f;

    #pragma unroll
    for (int s = 0; s < NS - 1; s++) {
        load_stage(s, s, tid, sbase, m0, n0);
        CP_COMMIT();
    }

    #pragma unroll 1
    for (int ks = 0; ks < KSTAGES; ks++) {
        if (ks < KSTAGES - 2) { CP_WAIT2(); } else { CP_WAIT0(); }
        __syncthreads();
        // issue next stage's loads immediately (writes buffer (ks-1)&3,
        // which every warp finished reading before this barrier)
        if (ks + NS - 1 < KSTAGES) {
            load_stage(ks + NS - 1, (ks + NS - 1) & (NS - 1), tid, sbase, m0, n0);
            CP_COMMIT();
        }
        const int stage = ks & (NS - 1);
        const uint32_t* As = (const uint32_t*)(smemf + stage * STAGE_FLOATS);
        const uint32_t* Bs = As + A_FLOATS;

        #pragma unroll
        for (int kk = 0; kk < 4; kk++) {
            const int kc = kk * 8;
            uint32_t afr[4][4];
            #pragma unroll
            for (int mt = 0; mt < 4; mt++) {
                const int r0 = wm * 64 + mt * 16 + gid;
                afr[mt][0] = As[r0 * ROWF + kc + tig];
                afr[mt][1] = As[(r0 + 8) * ROWF + kc + tig];
                afr[mt][2] = As[r0 * ROWF + kc + tig + 4];
                afr[mt][3] = As[(r0 + 8) * ROWF + kc + tig + 4];
            }
            #pragma unroll
            for (int g = 0; g < 4; g++) {
                const uint32_t* Bg = Bs + g * BG_FLOATS;
                uint32_t bfr[2][2];
                #pragma unroll
                for (int nt = 0; nt < 2; nt++) {
                    const int nb = wn * 16 + nt * 8 + gid;
                    bfr[nt][0] = Bg[nb * ROWF + kc + tig];
                    bfr[nt][1] = Bg[nb * ROWF + kc + tig + 4];
                }
                #pragma unroll
                for (int mt = 0; mt < 4; mt++)
                    #pragma unroll
                    for (int nt = 0; nt < 2; nt++)
                        mma_tf32(acc[g][mt][nt], afr[mt], bfr[nt]);
            }
        }
    }

    // ---------------- fused LSTM epilogue (registers only) ----------------
    #pragma unroll
    for (int nt = 0; nt < 2; nt++) {
        const int col = n0 + wn * 16 + nt * 8 + tig * 2;
        const float2 bf2 = *(const float2*)(bf + col);
        const float2 bi2 = *(const float2*)(bi + col);
        const float2 bc2 = *(const float2*)(bc + col);
        const float2 bo2 = *(const float2*)(bo + col);
        #pragma unroll
        for (int mt = 0; mt < 4; mt++) {
            const int row0 = m0 + wm * 64 + mt * 16 + gid;
            #pragma unroll
            for (int half = 0; half < 2; half++) {
                const int row = row0 + half * 8;
                const int ci = half * 2;
                const float2 cp = *(const float2*)(c_prev + (size_t)row * H_DIM + col);
                float hh[2], cc[2];
                #pragma unroll
                for (int j = 0; j < 2; j++) {
                    const float gf = acc[0][mt][nt][ci + j] + (j ? bf2.y : bf2.x);
                    const float gi = acc[1][mt][nt][ci + j] + (j ? bi2.y : bi2.x);
                    const float gc = acc[2][mt][nt][ci + j] + (j ? bc2.y : bc2.x);
                    const float go = acc[3][mt][nt][ci + j] + (j ? bo2.y : bo2.x);
                    const float f = sigmoidf_(gf);
                    const float i = sigmoidf_(gi);
                    const float ct = tanhf_(gc);
                    const float o = sigmoidf_(go);
                    const float c = f * (j ? cp.y : cp.x) + i * ct;
                    cc[j] = c;
                    hh[j] = o * tanhf_(c);
                }
                *(float2*)(out + (size_t)row * H_DIM + col) = make_float2(hh[0], hh[1]);
                *(float2*)(out + HOUT_OFF + (size_t)row * H_DIM + col) = make_float2(cc[0], cc[1]);
            }
        }
    }
}

extern "C" void kernel_launch(void* const* d_in, const int* in_sizes, int n_in,
                              void* d_out, int out_size) {
    const float* x_t    = (const float*)d_in[0];
    const float* h_prev = (const float*)d_in[1];
    const float* c_prev = (const float*)d_in[2];
    const float* W_f    = (const float*)d_in[3];
    const float* b_f    = (const float*)d_in[4];
    const float* W_i    = (const float*)d_in[5];
    const float* b_i    = (const float*)d_in[6];
    const float* W_c    = (const float*)d_in[7];
    const float* b_c    = (const float*)d_in[8];
    const float* W_o    = (const float*)d_in[9];
    const float* b_o    = (const float*)d_in[10];
    float* out = (float*)d_out;

    // 1) round all GEMM operands to tf32 once
    prepass_kernel<<<2048, 256>>>(
        (const float4*)x_t, (const float4*)h_prev,
        (const float4*)W_f, (const float4*)W_i,
        (const float4*)W_c, (const float4*)W_o);

    // 2) fused GEMM + LSTM epilogue
    cudaFuncSetAttribute(lstm_mma_kernel,
                         cudaFuncAttributeMaxDynamicSharedMemorySize, SMEM_TOTAL);
    dim3 grid(B_DIM / TM, H_DIM / TN);   // (32, 32)
    lstm_mma_kernel<<<grid, NTHREADS, SMEM_TOTAL>>>(
        c_prev, b_f, b_i, b_c, b_o, out);
}

// round 11
// speedup vs baseline: 1.0880x; 1.0364x over previous
#include <cuda_runtime.h>
#include <cstdint>

// ---------------- problem constants ----------------
#define B_DIM 4096
#define H_DIM 2048
#define C_DIM 4096              // K dimension (H + I)
#define TM 128                  // CTA M tile
#define TN 64                   // CTA N tile (per gate; x4 gates)
#define TK 64                   // K per stage (doubled: fewer sync points)
#define KSTAGES (C_DIM / TK)    // 64
#define NS 2                    // pipeline stages
#define NTHREADS 256            // 8 warps: 2 over M x 4 over N

// padded smem layout: rows of 68 floats (272B) -> conflict-free frag loads (68 % 32 == 4)
#define ROWF 68
#define A_FLOATS (TM * ROWF)            // 8704 floats
#define BG_FLOATS (TN * ROWF)           // 4352 floats
#define STAGE_FLOATS (A_FLOATS + 4 * BG_FLOATS)   // 26112 floats = 104448 B
#define SMEM_TOTAL (NS * STAGE_FLOATS * 4)        // 208896 B

#define HOUT_OFF 8388608        // 4096*2048 ; c_t follows h_t in d_out

// ---------- pre-rounded (tf32-rna) operand scratch ----------
__device__ float g_W[4ll * 2048 * 4096];   // 4 gates x [2048][4096]
__device__ float g_A[4096ll * 4096];       // [B][h_prev | x_t]

__device__ __forceinline__ uint32_t smem_u32(const void* p) {
    uint32_t a;
    asm("{ .reg .u64 t; cvta.to.shared.u64 t, %1; cvt.u32.u64 %0, t; }" : "=r"(a) : "l"(p));
    return a;
}

#define CP_ASYNC16(dst, src) \
    asm volatile("cp.async.cg.shared.global [%0], [%1], 16;" :: "r"(dst), "l"(src) : "memory")
#define CP_COMMIT() asm volatile("cp.async.commit_group;" ::: "memory")
#define CP_WAIT0()  asm volatile("cp.async.wait_group 0;" ::: "memory")

__device__ __forceinline__ float f2tf32f(float x) {
    uint32_t r;
    asm("cvt.rna.tf32.f32 %0, %1;" : "=r"(r) : "f"(x));
    return __uint_as_float(r);
}

__device__ __forceinline__ void mma_tf32(float* c, const uint32_t* a, const uint32_t* b) {
    asm volatile(
        "mma.sync.aligned.m16n8k8.row.col.f32.tf32.tf32.f32 "
        "{%0,%1,%2,%3}, {%4,%5,%6,%7}, {%8,%9}, {%0,%1,%2,%3};"
        : "+f"(c[0]), "+f"(c[1]), "+f"(c[2]), "+f"(c[3])
        : "r"(a[0]), "r"(a[1]), "r"(a[2]), "r"(a[3]), "r"(b[0]), "r"(b[1]));
}

__device__ __forceinline__ float sigmoidf_(float x) {
    return 1.0f / (1.0f + __expf(-x));
}
__device__ __forceinline__ float tanhf_(float x) {
    float a = fabsf(x);
    float e = __expf(-2.0f * a);
    float t = (1.0f - e) / (1.0f + e);
    return x < 0.0f ? -t : t;
}

// ---------------- prepass: round everything to tf32 (rna) once ----------------
#define W_F4 8388608
#define A_F4 4194304
#define TOT_F4 (W_F4 + A_F4)

__global__ void __launch_bounds__(256) prepass_kernel(
    const float4* __restrict__ x_t, const float4* __restrict__ h_prev,
    const float4* __restrict__ Wf, const float4* __restrict__ Wi,
    const float4* __restrict__ Wc, const float4* __restrict__ Wo)
{
    float4* __restrict__ gw = (float4*)g_W;
    float4* __restrict__ ga = (float4*)g_A;
    const int stride = gridDim.x * blockDim.x;
    for (long long i = blockIdx.x * blockDim.x + threadIdx.x; i < TOT_F4; i += stride) {
        float4 v;
        float4* dst;
        if (i < W_F4) {
            const long long g = i >> 21;
            const long long r = i & 2097151;
            const float4* wp = (g == 0) ? Wf : (g == 1) ? Wi : (g == 2) ? Wc : Wo;
            v = wp[r];
            dst = gw + i;
        } else {
            const long long j = i - W_F4;
            const long long row = j >> 10;
            const long long c4 = j & 1023;
            v = (c4 < 512) ? h_prev[row * 512 + c4] : x_t[row * 512 + (c4 - 512)];
            dst = ga + j;
        }
        v.x = f2tf32f(v.x); v.y = f2tf32f(v.y);
        v.z = f2tf32f(v.z); v.w = f2tf32f(v.w);
        *dst = v;
    }
}

// issue cp.async for one K-stage of TK=64 (all 256 threads participate)
__device__ __forceinline__ void load_stage(int ks, int stage, int tid, uint32_t sbase,
                                           int m0, int n0)
{
    const int k0 = ks * TK;
    const uint32_t stg = sbase + (uint32_t)stage * (STAGE_FLOATS * 4);
    const float* asrc = g_A + (size_t)m0 * C_DIM + k0;
    // A tile: 128 rows x 16 x 16B chunks = 2048; 8 per thread
    #pragma unroll
    for (int i = 0; i < 8; i++) {
        const int c = tid + i * NTHREADS;
        const int row = c >> 4;
        const int c16 = c & 15;
        const uint32_t dst = stg + (uint32_t)(row * (ROWF * 4) + c16 * 16);
        CP_ASYNC16(dst, asrc + (size_t)row * C_DIM + c16 * 4);
    }
    // W tiles: 4 gates x 64 rows x 16 chunks = 4096; 16 per thread
    #pragma unroll
    for (int i = 0; i < 16; i++) {
        const int idx = tid + i * NTHREADS;      // 0..4095
        const int g = idx >> 10;
        const int rem = idx & 1023;
        const int row = rem >> 4;
        const int c16 = rem & 15;
        const float* wp = g_W + (size_t)g * (2048ll * 4096);
        const uint32_t dst = stg + (uint32_t)(A_FLOATS * 4 + g * (BG_FLOATS * 4)
                                              + row * (ROWF * 4) + c16 * 16);
        CP_ASYNC16(dst, wp + (size_t)(n0 + row) * C_DIM + k0 + c16 * 4);
    }
}

__global__ void __launch_bounds__(NTHREADS, 1) lstm_mma_kernel(
    const float* __restrict__ c_prev,
    const float* __restrict__ bf, const float* __restrict__ bi,
    const float* __restrict__ bc, const float* __restrict__ bo,
    float* __restrict__ out)
{
    extern __shared__ float smemf[];
    const uint32_t sbase = smem_u32(smemf);
    const int tid = threadIdx.x;
    const int wid = tid >> 5;
    const int lane = tid & 31;
    const int wm = wid & 1;      // 2 warps over M (64 rows each, mt=4)
    const int wn = wid >> 1;     // 4 warps over N (16 cols each, nt=2)
    const int gid = lane >> 2;   // mma groupID
    const int tig = lane & 3;    // mma threadID_in_group
    const int m0 = blockIdx.x * TM;
    const int n0 = blockIdx.y * TN;

    // accumulators: [gate][mt=4][nt=2][4] = 128 floats
    float acc[4][4][2][4];
    #pragma unroll
    for (int g = 0; g < 4; g++)
        #pragma unroll
        for (int mt = 0; mt < 4; mt++)
            #pragma unroll
            for (int nt = 0; nt < 2; nt++)
                #pragma unroll
                for (int r = 0; r < 4; r++) acc[g][mt][nt][r] = 0.0f;

    // prologue: stage 0
    load_stage(0, 0, tid, sbase, m0, n0);
    CP_COMMIT();

    #pragma unroll 1
    for (int ks = 0; ks < KSTAGES; ks++) {
        CP_WAIT0();                // stage ks landed (only group in flight)
        __syncthreads();           // publish stage ks; protect buffer (ks+1)&1
        if (ks + 1 < KSTAGES) {
            load_stage(ks + 1, (ks + 1) & 1, tid, sbase, m0, n0);
            CP_COMMIT();
        }
        const uint32_t* As = (const uint32_t*)(smemf + (ks & 1) * STAGE_FLOATS);
        const uint32_t* Bs = As + A_FLOATS;

        #pragma unroll
        for (int kk = 0; kk < 8; kk++) {
            const int kc = kk * 8;
            uint32_t afr[4][4];
            #pragma unroll
            for (int mt = 0; mt < 4; mt++) {
                const int r0 = wm * 64 + mt * 16 + gid;
                afr[mt][0] = As[r0 * ROWF + kc + tig];
                afr[mt][1] = As[(r0 + 8) * ROWF + kc + tig];
                afr[mt][2] = As[r0 * ROWF + kc + tig + 4];
                afr[mt][3] = As[(r0 + 8) * ROWF + kc + tig + 4];
            }
            #pragma unroll
            for (int g = 0; g < 4; g++) {
                const uint32_t* Bg = Bs + g * BG_FLOATS;
                uint32_t bfr[2][2];
                #pragma unroll
                for (int nt = 0; nt < 2; nt++) {
                    const int nb = wn * 16 + nt * 8 + gid;
                    bfr[nt][0] = Bg[nb * ROWF + kc + tig];
                    bfr[nt][1] = Bg[nb * ROWF + kc + tig + 4];
                }
                #pragma unroll
                for (int mt = 0; mt < 4; mt++)
                    #pragma unroll
                    for (int nt = 0; nt < 2; nt++)
                        mma_tf32(acc[g][mt][nt], afr[mt], bfr[nt]);
            }
        }
    }

    // ---------------- fused LSTM epilogue (registers only) ----------------
    #pragma unroll
    for (int nt = 0; nt < 2; nt++) {
        const int col = n0 + wn * 16 + nt * 8 + tig * 2;
        const float2 bf2 = *(const float2*)(bf + col);
        const float2 bi2 = *(const float2*)(bi + col);
        const float2 bc2 = *(const float2*)(bc + col);
        const float2 bo2 = *(const float2*)(bo + col);
        #pragma unroll
        for (int mt = 0; mt < 4; mt++) {
            const int row0 = m0 + wm * 64 + mt * 16 + gid;
            #pragma unroll
            for (int half = 0; half < 2; half++) {
                const int row = row0 + half * 8;
                const int ci = half * 2;
                const float2 cp = *(const float2*)(c_prev + (size_t)row * H_DIM + col);
                float hh[2], cc[2];
                #pragma unroll
                for (int j = 0; j < 2; j++) {
                    const float gf = acc[0][mt][nt][ci + j] + (j ? bf2.y : bf2.x);
                    const float gi = acc[1][mt][nt][ci + j] + (j ? bi2.y : bi2.x);
                    const float gc = acc[2][mt][nt][ci + j] + (j ? bc2.y : bc2.x);
                    const float go = acc[3][mt][nt][ci + j] + (j ? bo2.y : bo2.x);
                    const float f = sigmoidf_(gf);
                    const float i = sigmoidf_(gi);
                    const float ct = tanhf_(gc);
                    const float o = sigmoidf_(go);
                    const float c = f * (j ? cp.y : cp.x) + i * ct;
                    cc[j] = c;
                    hh[j] = o * tanhf_(c);
                }
                *(float2*)(out + (size_t)row * H_DIM + col) = make_float2(hh[0], hh[1]);
                *(float2*)(out + HOUT_OFF + (size_t)row * H_DIM + col) = make_float2(cc[0], cc[1]);
            }
        }
    }
}

extern "C" void kernel_launch(void* const* d_in, const int* in_sizes, int n_in,
                              void* d_out, int out_size) {
    const float* x_t    = (const float*)d_in[0];
    const float* h_prev = (const float*)d_in[1];
    const float* c_prev = (const float*)d_in[2];
    const float* W_f    = (const float*)d_in[3];
    const float* b_f    = (const float*)d_in[4];
    const float* W_i    = (const float*)d_in[5];
    const float* b_i    = (const float*)d_in[6];
    const float* W_c    = (const float*)d_in[7];
    const float* b_c    = (const float*)d_in[8];
    const float* W_o    = (const float*)d_in[9];
    const float* b_o    = (const float*)d_in[10];
    float* out = (float*)d_out;

    // 1) round all GEMM operands to tf32 once
    prepass_kernel<<<2048, 256>>>(
        (const float4*)x_t, (const float4*)h_prev,
        (const float4*)W_f, (const float4*)W_i,
        (const float4*)W_c, (const float4*)W_o);

    // 2) fused GEMM + LSTM epilogue
    cudaFuncSetAttribute(lstm_mma_kernel,
                         cudaFuncAttributeMaxDynamicSharedMemorySize, SMEM_TOTAL);
    dim3 grid(B_DIM / TM, H_DIM / TN);   // (32, 32)
    lstm_mma_kernel<<<grid, NTHREADS, SMEM_TOTAL>>>(
        c_prev, b_f, b_i, b_c, b_o, out);
}